// round 11
// baseline (speedup 1.0000x reference)
#include <cuda_runtime.h>

// Problem constants
#define HH 64
#define WW 2048
#define LL (HH*WW)
#define BB 4
#define NO 32          // STEM
#define KF 45          // 5 ch * 9 knn

// Tile: 8 rows x 32 cols = 256 pixels, 256 threads, 1 px/thread
#define TW 32
#define TH 8
#define NT 256

// Shared tiles with halos
#define XS_R 36               // 32 + 2*2
#define XS_NROW 12            // 8 + 2*2
#define PS_R 38               // 32 + 2*3
#define PS_NROW 14            // 8 + 2*3
#define XS_C (XS_NROW*XS_R)   // 432 floats per channel
#define PS_C (PS_NROW*PS_R)   // 532
#define XS_TOT (5*XS_C)       // 2160
#define PS_TOT (5*PS_C)       // 2660

typedef unsigned long long u64;

__device__ __forceinline__ u64 pack2(float lo, float hi) {
    u64 r; asm("mov.b64 %0, {%1, %2};" : "=l"(r) : "f"(lo), "f"(hi)); return r;
}
__device__ __forceinline__ void unpack2(u64 v, float& lo, float& hi) {
    asm("mov.b64 {%0, %1}, %2;" : "=f"(lo), "=f"(hi) : "l"(v));
}
// d = a*b + d  (packed fp32x2, Blackwell)
__device__ __forceinline__ void fma2(u64& d, u64 a, u64 b) {
    asm("fma.rn.f32x2 %0, %1, %2, %3;" : "=l"(d) : "l"(a), "l"(b), "l"(d));
}
__device__ __forceinline__ float sqrt_approx(float x) {
    float r; asm("sqrt.approx.f32 %0, %1;" : "=f"(r) : "f"(x)); return r;
}

// atan poly on [0,1], minimax degree-17 (odd), ~1e-7 abs err
__device__ __forceinline__ float atan_poly(float a) {
    float s = a * a;
    float r =            2.78569828e-3f;
    r = fmaf(r, s, -1.58660226e-2f);
    r = fmaf(r, s,  4.24722321e-2f);
    r = fmaf(r, s, -7.49753043e-2f);
    r = fmaf(r, s,  1.06448799e-1f);
    r = fmaf(r, s, -1.42070308e-1f);
    r = fmaf(r, s,  1.99934542e-1f);
    r = fmaf(r, s, -3.33331466e-1f);
    r = r * s;
    return fmaf(r, a, a);
}
// atan2 restricted to y>=0, x>=0 (first quadrant). atan2(0,0)=0 like jnp.
__device__ __forceinline__ float atan2_pos(float y, float x) {
    float mx = fmaxf(y, x);
    float mn = fminf(y, x);
    float r  = __fdividef(mn, fmaxf(mx, 1e-37f));
    float a  = atan_poly(r);
    if (y > x) a = 1.57079632679f - a;
    return a;
}

// Sorted-ascending insertion. Values advance via pure FMNMX chain:
//   bv'[k] = min(bv[k], max(bv[k-1], d)),  bv'[0] = min(bv[0], d)
// which is exactly insertion with strict '<' (ties keep earlier scan index =
// lax.top_k lower-index-first). Index shift uses FSETP+SEL off the critical path.
template<int D>
__device__ __forceinline__ void ins(float (&bv)[D], int (&bi)[D], float d, int off) {
    bool p[D];
#pragma unroll
    for (int k = 0; k < D; k++) p[k] = d < bv[k];
#pragma unroll
    for (int k = D - 1; k >= 1; k--)
        bi[k] = p[k-1] ? bi[k-1] : (p[k] ? off : bi[k]);
    bi[0] = p[0] ? off : bi[0];
#pragma unroll
    for (int k = D - 1; k >= 1; k--)
        bv[k] = fminf(bv[k], fmaxf(bv[k-1], d));
    bv[0] = fminf(bv[0], d);
}

struct __align__(16) Smem {
    float XS[XS_TOT];
    float PS[PS_TOT];
    float WT0[KF*NO];   // WT[k][o] = wr[o][k]
    float WT1[KF*NO];
};

// One k-column of the mini-GEMM: acc[j] packs outputs (2j, 2j+1).
__device__ __forceinline__ void gemm_col(u64 (&acc)[16], float g, const float* wk) {
    u64 gg = pack2(g, g);
    const ulonglong2* wp = (const ulonglong2*)wk;   // 16B-aligned (k*NO*4 = 128B stride)
#pragma unroll
    for (int j = 0; j < 8; j++) {
        ulonglong2 w2 = wp[j];
        fma2(acc[2*j],   gg, w2.x);
        fma2(acc[2*j+1], gg, w2.y);
    }
}

__global__ void __launch_bounds__(NT, 3) knn_conv_kernel(
    const float* __restrict__ x, const float* __restrict__ prex,
    const float* __restrict__ rw, const float* __restrict__ prw,
    float* __restrict__ out)
{
    __shared__ Smem S;

    const int tid = threadIdx.x;
    const int w0  = blockIdx.x * TW;
    const int h0  = blockIdx.y * TH;
    const int b   = blockIdx.z;

    // ---- cooperative tile loads (zero-padded halos) ----
    for (int i = tid; i < XS_TOT; i += NT) {
        int c   = i / XS_C;
        int rem = i - c * XS_C;
        int r   = rem / XS_R;
        int col = rem - r * XS_R;
        int gh = h0 - 2 + r, gw = w0 - 2 + col;
        float v = 0.f;
        if ((unsigned)gh < HH && (unsigned)gw < WW)
            v = x[(((size_t)b*5 + c)*HH + gh)*WW + gw];
        S.XS[i] = v;
    }
    for (int i = tid; i < PS_TOT; i += NT) {
        int c   = i / PS_C;
        int rem = i - c * PS_C;
        int r   = rem / PS_R;
        int col = rem - r * PS_R;
        int gh = h0 - 3 + r, gw = w0 - 3 + col;
        float v = 0.f;
        if ((unsigned)gh < HH && (unsigned)gw < WW)
            v = prex[(((size_t)b*5 + c)*HH + gh)*WW + gw];
        S.PS[i] = v;
    }
    // weights: wr[o][k] -> WT[k][o]
    for (int i = tid; i < NO*KF; i += NT) {
        int o = i / KF;
        int k = i - o * KF;
        S.WT0[k*NO + o] = rw[i];
        S.WT1[k*NO + o] = prw[i];
    }
    __syncthreads();

    const int tx = tid & 31, ty = tid >> 5;
    const int wb    = ty*XS_R + tx;        // 5x5 window origin in XS
    const int ctr_i = wb + 2*XS_R + 2;     // center offset (ch-0 plane)
    const int pwb   = ty*PS_R + tx;        // 7x7 window origin in PS
    const float ctr = S.XS[ctr_i];

    // ---- both selections, interleaved in one basic block (2 indep chains) ----
    float bv[8]; int bo[8];
    float pv[9]; int po[9];
#pragma unroll
    for (int k = 0; k < 8; k++) { bv[k] = 3.0e38f; bo[k] = ctr_i; }
#pragma unroll
    for (int k = 0; k < 9; k++) { pv[k] = 3.0e38f; po[k] = pwb; }
#pragma unroll
    for (int s = 0; s < 49; s++) {
        {   // pre: 9 smallest of 49
            const int off = pwb + (s/7)*PS_R + (s%7);
            ins<9>(pv, po, fabsf(S.PS[off] - ctr), off);
        }
        if (s < 25 && s != 12) {   // x: 8 smallest of 24 (center excluded)
            const int off = wb + (s/5)*XS_R + (s%5);
            ins<8>(bv, bo, fabsf(S.XS[off] - ctr), off);
        }
    }

    u64 acc[16];

    // ================= x path GEMM =================
    {
#pragma unroll
        for (int j = 0; j < 16; j++) acc[j] = 0ull;
        // rank 0 = center (diff[center] set to -1 in reference)
#pragma unroll
        for (int c = 0; c < 5; c++)
            gemm_col(acc, S.XS[c*XS_C + ctr_i], S.WT0 + (c*9)*NO);
#pragma unroll
        for (int r = 0; r < 8; r++) {
            const int off = bo[r];
#pragma unroll
            for (int c = 0; c < 5; c++)
                gemm_col(acc, S.XS[c*XS_C + off], S.WT0 + (c*9 + 1 + r)*NO);
        }

        float* op = out + ((size_t)b*NO)*LL + (size_t)(h0+ty)*WW + (w0+tx);
#pragma unroll
        for (int j = 0; j < 16; j++) {
            float lo, hi; unpack2(acc[j], lo, hi);
            op[(size_t)(2*j  )*LL] = fmaxf(lo, 0.f);
            op[(size_t)(2*j+1)*LL] = fmaxf(hi, 0.f);
        }
    }

    // ================= pre path GEMM =================
    {
#pragma unroll
        for (int j = 0; j < 16; j++) acc[j] = 0ull;
        const float a1 = S.XS[1*XS_C + ctr_i];
        const float a2 = S.XS[2*XS_C + ctr_i];
        const float a3 = S.XS[3*XS_C + ctr_i];
#pragma unroll
        for (int r = 0; r < 9; r++) {
            const int off = po[r];
            const float p1 = S.PS[PS_C   + off];
            const float p2 = S.PS[2*PS_C + off];
            const float p3 = S.PS[3*PS_C + off];
            const float ddx = p1 - a1, ddy = p2 - a2, ddz = p3 - a3;
            const float xy = ddx*ddx + ddy*ddy;
            const float zz = ddz*ddz;
            const float rr = sqrt_approx(xy + zz);
            const float th = atan2_pos(sqrt_approx(xy), zz);
            const float ph = atan2_pos(ddy*ddy, ddx*ddx);
            gemm_col(acc, S.PS[off],          S.WT1 + ( 0 + r)*NO);
            gemm_col(acc, rr,                 S.WT1 + ( 9 + r)*NO);
            gemm_col(acc, th,                 S.WT1 + (18 + r)*NO);
            gemm_col(acc, ph,                 S.WT1 + (27 + r)*NO);
            gemm_col(acc, S.PS[4*PS_C + off], S.WT1 + (36 + r)*NO);
        }

        float* op = out + (size_t)BB*NO*LL
                  + ((size_t)b*NO)*LL + (size_t)(h0+ty)*WW + (w0+tx);
#pragma unroll
        for (int j = 0; j < 16; j++) {
            float lo, hi; unpack2(acc[j], lo, hi);
            op[(size_t)(2*j  )*LL] = fmaxf(lo, 0.f);
            op[(size_t)(2*j+1)*LL] = fmaxf(hi, 0.f);
        }
    }
}

extern "C" void kernel_launch(void* const* d_in, const int* in_sizes, int n_in,
                              void* d_out, int out_size)
{
    const float* x    = (const float*)d_in[0];
    const float* prex = (const float*)d_in[1];
    const float* rw   = (const float*)d_in[2];
    const float* prw  = (const float*)d_in[3];
    float* out = (float*)d_out;

    static bool attr_set = false;
    if (!attr_set) {
        cudaFuncSetAttribute(knn_conv_kernel,
                             cudaFuncAttributePreferredSharedMemoryCarveout, 60);
        attr_set = true;
    }

    dim3 grid(WW/TW, HH/TH, BB);
    knn_conv_kernel<<<grid, NT>>>(x, prex, rw, prw, out);
}

// round 16
// speedup vs baseline: 1.1814x; 1.1814x over previous
#include <cuda_runtime.h>

// Problem constants
#define HH 64
#define WW 2048
#define LL (HH*WW)
#define BB 4
#define NO 32          // STEM
#define KF 45          // 5 ch * 9 knn

// Tile: 8 rows x 32 cols = 256 pixels; 512 threads (2 paths x 256 pixels)
#define TW 32
#define TH 8
#define NPIX 256
#define NT 512

// Shared tiles with halos
#define XS_R 36               // 32 + 2*2
#define XS_NROW 12            // 8 + 2*2
#define PS_R 38               // 32 + 2*3
#define PS_NROW 14            // 8 + 2*3
#define XS_C (XS_NROW*XS_R)   // 432 floats per channel
#define PS_C (PS_NROW*PS_R)   // 532
#define XS_TOT (5*XS_C)       // 2160
#define PS_TOT (5*PS_C)       // 2660

typedef unsigned long long u64;

__device__ __forceinline__ u64 pack2(float lo, float hi) {
    u64 r; asm("mov.b64 %0, {%1, %2};" : "=l"(r) : "f"(lo), "f"(hi)); return r;
}
__device__ __forceinline__ void unpack2(u64 v, float& lo, float& hi) {
    asm("mov.b64 {%0, %1}, %2;" : "=f"(lo), "=f"(hi) : "l"(v));
}
// d = a*b + d  (packed fp32x2, Blackwell)
__device__ __forceinline__ void fma2(u64& d, u64 a, u64 b) {
    asm("fma.rn.f32x2 %0, %1, %2, %3;" : "=l"(d) : "l"(a), "l"(b), "l"(d));
}
__device__ __forceinline__ float sqrt_approx(float x) {
    float r; asm("sqrt.approx.f32 %0, %1;" : "=f"(r) : "f"(x)); return r;
}

// atan poly on [0,1], minimax degree-17 (odd), ~1e-7 abs err
__device__ __forceinline__ float atan_poly(float a) {
    float s = a * a;
    float r =            2.78569828e-3f;
    r = fmaf(r, s, -1.58660226e-2f);
    r = fmaf(r, s,  4.24722321e-2f);
    r = fmaf(r, s, -7.49753043e-2f);
    r = fmaf(r, s,  1.06448799e-1f);
    r = fmaf(r, s, -1.42070308e-1f);
    r = fmaf(r, s,  1.99934542e-1f);
    r = fmaf(r, s, -3.33331466e-1f);
    r = r * s;
    return fmaf(r, a, a);
}
// atan2 restricted to y>=0, x>=0 (first quadrant). atan2(0,0)=0 like jnp.
__device__ __forceinline__ float atan2_pos(float y, float x) {
    float mx = fmaxf(y, x);
    float mn = fminf(y, x);
    float r  = __fdividef(mn, fmaxf(mx, 1e-37f));
    float a  = atan_poly(r);
    if (y > x) a = 1.57079632679f - a;
    return a;
}

// Sorted-ascending insertion. Values advance via pure FMNMX chain:
//   bv'[k] = min(bv[k], max(bv[k-1], d)),  bv'[0] = min(bv[0], d)
// == insertion with strict '<' (ties keep earlier scan index = lax.top_k rule).
// Index shift uses FSETP+SEL off the value critical path.
template<int D>
__device__ __forceinline__ void ins(float (&bv)[D], int (&bi)[D], float d, int off) {
    bool p[D];
#pragma unroll
    for (int k = 0; k < D; k++) p[k] = d < bv[k];
#pragma unroll
    for (int k = D - 1; k >= 1; k--)
        bi[k] = p[k-1] ? bi[k-1] : (p[k] ? off : bi[k]);
    bi[0] = p[0] ? off : bi[0];
#pragma unroll
    for (int k = D - 1; k >= 1; k--)
        bv[k] = fminf(bv[k], fmaxf(bv[k-1], d));
    bv[0] = fminf(bv[0], d);
}

struct __align__(16) Smem {
    float XS[XS_TOT];
    float PS[PS_TOT];
    float WT0[KF*NO];   // WT[k][o] = wr[o][k]
    float WT1[KF*NO];
};

// One k-column of the mini-GEMM: acc[j] packs outputs (2j, 2j+1).
__device__ __forceinline__ void gemm_col(u64 (&acc)[16], float g, const float* wk) {
    u64 gg = pack2(g, g);
    const ulonglong2* wp = (const ulonglong2*)wk;   // 16B-aligned (k*NO*4 = 128B stride)
#pragma unroll
    for (int j = 0; j < 8; j++) {
        ulonglong2 w2 = wp[j];
        fma2(acc[2*j],   gg, w2.x);
        fma2(acc[2*j+1], gg, w2.y);
    }
}

__global__ void __launch_bounds__(NT, 2) knn_conv_kernel(
    const float* __restrict__ x, const float* __restrict__ prex,
    const float* __restrict__ rw, const float* __restrict__ prw,
    float* __restrict__ out)
{
    __shared__ Smem S;

    const int tid = threadIdx.x;
    const int w0  = blockIdx.x * TW;
    const int h0  = blockIdx.y * TH;
    const int b   = blockIdx.z;

    // ---- cooperative tile loads, channel-outer (no big div/mod) ----
    // XS: 432 elems/channel, 512 threads -> one conditional load per channel
    if (tid < XS_C) {
        const int r   = tid / XS_R;
        const int col = tid - r * XS_R;
        const int gh = h0 - 2 + r, gw = w0 - 2 + col;
        const bool ok = ((unsigned)gh < HH) & ((unsigned)gw < WW);
        const size_t gbase = ((size_t)b*5*HH + gh)*WW + gw;
#pragma unroll
        for (int c = 0; c < 5; c++) {
            float v = 0.f;
            if (ok) v = x[gbase + (size_t)c*HH*WW];
            S.XS[c*XS_C + tid] = v;
        }
    }
    // PS: 532 elems/channel -> iterations at tid and tid+512
#pragma unroll
    for (int base = 0; base < PS_C; base += NT) {
        const int i = base + tid;
        if (i < PS_C) {
            const int r   = i / PS_R;
            const int col = i - r * PS_R;
            const int gh = h0 - 3 + r, gw = w0 - 3 + col;
            const bool ok = ((unsigned)gh < HH) & ((unsigned)gw < WW);
            const size_t gbase = ((size_t)b*5*HH + gh)*WW + gw;
#pragma unroll
            for (int c = 0; c < 5; c++) {
                float v = 0.f;
                if (ok) v = prex[gbase + (size_t)c*HH*WW];
                S.PS[c*PS_C + i] = v;
            }
        }
    }
    // weights: wr[o][k] -> WT[k][o]; 1440 elems each
#pragma unroll
    for (int base = 0; base < NO*KF; base += NT) {
        const int i = base + tid;
        if (i < NO*KF) {
            const int o = i / KF;
            const int k = i - o * KF;
            S.WT0[k*NO + o] = rw[i];
            S.WT1[k*NO + o] = prw[i];
        }
    }
    __syncthreads();

    const int pix  = tid & (NPIX-1);
    const int path = tid >> 8;            // warps 0-7: x path, warps 8-15: pre path
    const int tx = pix & 31, ty = pix >> 5;
    const int wb    = ty*XS_R + tx;       // 5x5 window origin in XS
    const int ctr_i = wb + 2*XS_R + 2;    // center offset (ch-0 plane)
    const int pwb   = ty*PS_R + tx;       // 7x7 window origin in PS
    const float ctr = S.XS[ctr_i];

    u64 acc[16];
#pragma unroll
    for (int j = 0; j < 16; j++) acc[j] = 0ull;

    if (path == 0) {
        // ================= x path =================
        float bv[8]; int bo[8];
#pragma unroll
        for (int k = 0; k < 8; k++) { bv[k] = 3.0e38f; bo[k] = ctr_i; }
#pragma unroll
        for (int s = 0; s < 25; s++) {
            if (s == 12) continue;
            const int off = wb + (s/5)*XS_R + (s%5);
            ins<8>(bv, bo, fabsf(S.XS[off] - ctr), off);
        }

        // rank 0 = center (diff[center] = -1 in reference)
#pragma unroll
        for (int c = 0; c < 5; c++)
            gemm_col(acc, S.XS[c*XS_C + ctr_i], S.WT0 + (c*9)*NO);
#pragma unroll
        for (int r = 0; r < 8; r++) {
            const int off = bo[r];
#pragma unroll
            for (int c = 0; c < 5; c++)
                gemm_col(acc, S.XS[c*XS_C + off], S.WT0 + (c*9 + 1 + r)*NO);
        }

        float* op = out + ((size_t)b*NO)*LL + (size_t)(h0+ty)*WW + (w0+tx);
#pragma unroll
        for (int j = 0; j < 16; j++) {
            float lo, hi; unpack2(acc[j], lo, hi);
            op[(size_t)(2*j  )*LL] = fmaxf(lo, 0.f);
            op[(size_t)(2*j+1)*LL] = fmaxf(hi, 0.f);
        }
    } else {
        // ================= pre path =================
        float pv[9]; int po[9];
#pragma unroll
        for (int k = 0; k < 9; k++) { pv[k] = 3.0e38f; po[k] = pwb; }
#pragma unroll
        for (int s = 0; s < 49; s++) {
            const int off = pwb + (s/7)*PS_R + (s%7);
            ins<9>(pv, po, fabsf(S.PS[off] - ctr), off);
        }

        const float a1 = S.XS[1*XS_C + ctr_i];
        const float a2 = S.XS[2*XS_C + ctr_i];
        const float a3 = S.XS[3*XS_C + ctr_i];
#pragma unroll
        for (int r = 0; r < 9; r++) {
            const int off = po[r];
            const float p1 = S.PS[PS_C   + off];
            const float p2 = S.PS[2*PS_C + off];
            const float p3 = S.PS[3*PS_C + off];
            const float ddx = p1 - a1, ddy = p2 - a2, ddz = p3 - a3;
            const float xy = ddx*ddx + ddy*ddy;
            const float zz = ddz*ddz;
            const float rr = sqrt_approx(xy + zz);
            const float th = atan2_pos(sqrt_approx(xy), zz);
            const float ph = atan2_pos(ddy*ddy, ddx*ddx);
            gemm_col(acc, S.PS[off],          S.WT1 + ( 0 + r)*NO);
            gemm_col(acc, rr,                 S.WT1 + ( 9 + r)*NO);
            gemm_col(acc, th,                 S.WT1 + (18 + r)*NO);
            gemm_col(acc, ph,                 S.WT1 + (27 + r)*NO);
            gemm_col(acc, S.PS[4*PS_C + off], S.WT1 + (36 + r)*NO);
        }

        float* op = out + (size_t)BB*NO*LL
                  + ((size_t)b*NO)*LL + (size_t)(h0+ty)*WW + (w0+tx);
#pragma unroll
        for (int j = 0; j < 16; j++) {
            float lo, hi; unpack2(acc[j], lo, hi);
            op[(size_t)(2*j  )*LL] = fmaxf(lo, 0.f);
            op[(size_t)(2*j+1)*LL] = fmaxf(hi, 0.f);
        }
    }
}

extern "C" void kernel_launch(void* const* d_in, const int* in_sizes, int n_in,
                              void* d_out, int out_size)
{
    const float* x    = (const float*)d_in[0];
    const float* prex = (const float*)d_in[1];
    const float* rw   = (const float*)d_in[2];
    const float* prw  = (const float*)d_in[3];
    float* out = (float*)d_out;

    dim3 grid(WW/TW, HH/TH, BB);
    knn_conv_kernel<<<grid, NT>>>(x, prex, rw, prw, out);
}